// round 2
// baseline (speedup 1.0000x reference)
#include <cuda_runtime.h>

// NeighborhoodAttention 3D fp32, B=1, T=16, H=32, W=32, nh=8, D=128, window (3,7,7).
// CTA = (t, h, head), 128 threads = 4 warps, each warp owns 8 consecutive-w queries
// (full 32-w row per CTA). All queries in the CTA share clamped (st, sh), so the key
// set is 21 (dt,dh) rows x 32 w-positions. Each row (16KB) is staged in smem once;
// each warp loads each key vector ONCE into registers and FMAs against 8 resident
// Q vectors -> K/V bytes amortized 8x, global traffic amortized further by row reuse.

__global__ void __launch_bounds__(128) na3d_fwd(
    const float* __restrict__ Q, const float* __restrict__ K,
    const float* __restrict__ V, float* __restrict__ O)
{
    const int bx   = blockIdx.x;        // t*32 + h
    const int head = blockIdx.y;        // 0..7
    const int t = bx >> 5, h = bx & 31;
    const int tid  = threadIdx.x;
    const int warp = tid >> 5, lane = tid & 31;

    __shared__ float krow[32 * 128];    // one (dt,dh) row: 32 keys x 128 dims
    __shared__ float sc[32][148];       // scores / probs per query (147 keys, padded)

    const int st = min(max(t - 1, 0), 13);
    const int sh = min(max(h - 3, 0), 25);
    const float scale = 0.08838834764831845f;   // 128^-0.5

    const int w0 = warp << 3;

    // resident Q fragments (lane owns dims [4*lane, 4*lane+4))
    float4 q4[8];
    int    swq[8];
    float  mx[8];
#pragma unroll
    for (int i = 0; i < 8; ++i) {
        const int w = w0 + i;
        swq[i] = min(max(w - 3, 0), 25);
        const float* qp = Q + (((size_t)(t * 1024 + h * 32 + w) * 8 + head) << 7) + (lane << 2);
        float4 v = *(const float4*)qp;
        v.x *= scale; v.y *= scale; v.z *= scale; v.w *= scale;
        q4[i] = v;
        mx[i] = -1e30f;
    }
    const int wlo = swq[0];         // union of this warp's w-windows
    const int whi = swq[7] + 6;

    // ================= score phase =================
    for (int r = 0; r < 21; ++r) {
        const int dt = r / 7, dh = r - dt * 7;
        const float* src = K + (((size_t)((st + dt) * 1024 + (sh + dh) * 32) * 8 + head) << 7);
        __syncthreads();    // previous row's reads complete
#pragma unroll
        for (int j = 0; j < 8; ++j) {               // stage 16KB, coalesced
            const int g  = tid + (j << 7);          // granule 0..1023
            const int wp = g >> 5, d4 = g & 31;
            ((float4*)krow)[g] = ((const float4*)(src + wp * 1024))[d4];
        }
        __syncthreads();

        for (int wp = wlo; wp <= whi; ++wp) {
            const float4 k4 = ((const float4*)(krow + (wp << 7)))[lane];  // key -> regs, once
            // contiguous valid-query range for this key (warp-uniform)
            const int qlo = max(w0,     (wp <= 6)  ? 0  : (wp - 3)) - w0;
            const int qhi = min(w0 + 7, (wp >= 25) ? 31 : (wp + 3)) - w0;
#pragma unroll
            for (int i = 0; i < 8; ++i) {
                if (i < qlo || i > qhi) continue;   // warp-uniform predicate
                float s = q4[i].x * k4.x + q4[i].y * k4.y
                        + q4[i].z * k4.z + q4[i].w * k4.w;
#pragma unroll
                for (int o = 16; o; o >>= 1) s += __shfl_xor_sync(0xffffffffu, s, o);
                mx[i] = fmaxf(mx[i], s);
                if (lane == 0) sc[w0 + i][r * 7 + wp - swq[i]] = s;
            }
        }
    }
    __syncwarp();

    // ================= softmax =================
    float inv[8];
#pragma unroll
    for (int i = 0; i < 8; ++i) {
        float lsum = 0.f;
        for (int j = lane; j < 147; j += 32) {
            const float p = __expf(sc[w0 + i][j] - mx[i]);
            sc[w0 + i][j] = p;
            lsum += p;
        }
#pragma unroll
        for (int o = 16; o; o >>= 1) lsum += __shfl_xor_sync(0xffffffffu, lsum, o);
        inv[i] = 1.0f / lsum;
    }
    __syncwarp();

    // ================= PV phase =================
    float4 acc[8];
#pragma unroll
    for (int i = 0; i < 8; ++i) acc[i] = make_float4(0.f, 0.f, 0.f, 0.f);

    for (int r = 0; r < 21; ++r) {
        const int dt = r / 7, dh = r - dt * 7;
        const float* src = V + (((size_t)((st + dt) * 1024 + (sh + dh) * 32) * 8 + head) << 7);
        __syncthreads();
#pragma unroll
        for (int j = 0; j < 8; ++j) {
            const int g  = tid + (j << 7);
            const int wp = g >> 5, d4 = g & 31;
            ((float4*)krow)[g] = ((const float4*)(src + wp * 1024))[d4];
        }
        __syncthreads();

        for (int wp = wlo; wp <= whi; ++wp) {
            const float4 v4 = ((const float4*)(krow + (wp << 7)))[lane];
            const int qlo = max(w0,     (wp <= 6)  ? 0  : (wp - 3)) - w0;
            const int qhi = min(w0 + 7, (wp >= 25) ? 31 : (wp + 3)) - w0;
#pragma unroll
            for (int i = 0; i < 8; ++i) {
                if (i < qlo || i > qhi) continue;
                const float p = sc[w0 + i][r * 7 + wp - swq[i]];   // broadcast LDS.32
                acc[i].x += p * v4.x; acc[i].y += p * v4.y;
                acc[i].z += p * v4.z; acc[i].w += p * v4.w;
            }
        }
    }

#pragma unroll
    for (int i = 0; i < 8; ++i) {
        const int w = w0 + i;
        float* op = O + (((size_t)(t * 1024 + h * 32 + w) * 8 + head) << 7) + (lane << 2);
        float4 o4;
        o4.x = acc[i].x * inv[i]; o4.y = acc[i].y * inv[i];
        o4.z = acc[i].z * inv[i]; o4.w = acc[i].w * inv[i];
        *(float4*)op = o4;
    }
}

extern "C" void kernel_launch(void* const* d_in, const int* in_sizes, int n_in,
                              void* d_out, int out_size) {
    const float* q = (const float*)d_in[0];
    const float* k = (const float*)d_in[1];
    const float* v = (const float*)d_in[2];
    (void)in_sizes; (void)n_in; (void)out_size;
    dim3 grid(512, 8);          // (t*32+h), head
    na3d_fwd<<<grid, 128>>>(q, k, v, (float*)d_out);
}

// round 4
// speedup vs baseline: 1.4444x; 1.4444x over previous
#include <cuda_runtime.h>

// NA3D fp32, B=1, T=16, H=32, W=32, nh=8, D=128, window (3,7,7).
// CTA = (t, h-pair, head): 64 queries (2 h x 32 w), 512 threads, 16 warps.
// Warp = (hsub, 4 consecutive w queries). Lane = (q 0..3, dpart 0..7):
// lane owns query q's dims {4*dpart + 32*i}. Online fused max-free softmax:
// per staged (K,V) row: dot (8 FFMA2) -> 3-shfl butterfly -> ex2 -> masked p
// -> PV accumulate (8 FFMA2). No score storage, no data-dependent branches.

#define Tz 16
#define Hz 32
#define Wz 32
#define KST 132                      // padded floats per key in staged row
#define QSCALE 0.12751743f           // 128^-0.5 * log2(e)

typedef unsigned long long ull;

__device__ __forceinline__ void ffma2(ull& acc, ull a, ull b) {
    asm("fma.rn.f32x2 %0, %1, %2, %0;" : "+l"(acc) : "l"(a), "l"(b));
}
__device__ __forceinline__ ull pk2(float x, float y) {
    ull r; asm("mov.b64 %0, {%1, %2};" : "=l"(r) : "f"(x), "f"(y)); return r;
}
__device__ __forceinline__ float sum2(ull a) {
    float x, y; asm("mov.b64 {%0, %1}, %2;" : "=f"(x), "=f"(y) : "l"(a)); return x + y;
}
__device__ __forceinline__ float ex2(float x) {
    float r; asm("ex2.approx.f32 %0, %1;" : "=f"(r) : "f"(x)); return r;
}

__global__ void __launch_bounds__(512, 2) na3d_fwd(
    const float* __restrict__ Q, const float* __restrict__ K,
    const float* __restrict__ V, float* __restrict__ O)
{
    __shared__ __align__(16) float kbuf[32 * KST];
    __shared__ __align__(16) float vbuf[32 * KST];

    const int bx = blockIdx.x;               // t*16 + h0/2
    const int head = blockIdx.y;
    const int t = bx >> 4, h0 = (bx & 15) << 1;
    const int tid = threadIdx.x;
    const int warp = tid >> 5, lane = tid & 31;
    const int q = lane >> 3, dpart = lane & 7;

    const int hq = h0 + (warp & 1);           // this warp's query h
    const int w0 = (warp >> 1) << 2;          // first of 4 queries
    const int wq = w0 + q;

    const int st  = min(max(t - 1, 0), Tz - 3);
    const int hb  = min(max(h0 - 3, 0), Hz - 7);   // staged h-row base (union)
    const int sh  = min(max(hq - 3, 0), Hz - 7);   // this warp's h window start
    const int sw  = min(max(wq - 3, 0), Wz - 7);   // this lane's query w window start
    const int wlo = min(max(w0 - 3, 0), Wz - 7);   // warp w-union start (10 keys)

    // ---- Q fragment: 16 dims {4*dpart + 32*i}, pre-scaled by 1/sqrt(D)*log2e ----
    ull qr[8];
    {
        const float* qsrc = Q + ((size_t)((t * Hz + hq) * Wz + wq) * 8 + head) * 128
                              + (dpart << 2);
#pragma unroll
        for (int i = 0; i < 4; ++i) {
            float4 v = *(const float4*)(qsrc + (i << 5));
            qr[2*i]   = pk2(v.x * QSCALE, v.y * QSCALE);
            qr[2*i+1] = pk2(v.z * QSCALE, v.w * QSCALE);
        }
    }

    ull acc[8];
#pragma unroll
    for (int i = 0; i < 8; ++i) acc[i] = 0ull;
    float vsum = 0.f;

#pragma unroll 1
    for (int rr = 0; rr < 24; ++rr) {               // 3 dt x 8 union h-rows
        const int dt = rr >> 3, j = rr & 7;
        const int hh_u = hb + j;                    // unclamped union row
        const int hh = min(hh_u, Hz - 1);
        const size_t roff = ((size_t)(((st + dt) * Hz + hh) * Wz) * 8 + head) * 128;
        const float* ksrc = K + roff;
        const float* vsrc = V + roff;

        __syncthreads();
#pragma unroll
        for (int g0 = 0; g0 < 4; ++g0) {            // stage K row + V row (32KB)
            const int g = tid + (g0 << 9);          // 0..2047 float4 granules
            const int wp = (g >> 5) & 31, d4 = g & 31;
            const float4 val = (g < 1024)
                ? *((const float4*)(ksrc + wp * 1024) + d4)
                : *((const float4*)(vsrc + wp * 1024) + d4);
            float* dst = (g < 1024) ? kbuf : vbuf;
            *(float4*)(dst + wp * KST + (d4 << 2)) = val;
        }
        __syncthreads();

        if (hh_u >= sh && hh_u <= sh + 6) {         // warp-uniform row validity
#pragma unroll
            for (int kk = 0; kk < 10; ++kk) {
                const int wku = wlo + kk;           // unclamped key w
                const int wkey = min(wku, Wz - 1);
                const float* kp = kbuf + wkey * KST + (dpart << 2);

                ull a = 0ull, b = 0ull;             // 16-dim partial dot
#pragma unroll
                for (int i = 0; i < 4; ++i) {
                    const ulonglong2 k2 = *(const ulonglong2*)(kp + (i << 5));
                    ffma2(a, qr[2*i],   k2.x);
                    ffma2(b, qr[2*i+1], k2.y);
                }
                float s = sum2(a) + sum2(b);
#pragma unroll
                for (int o = 1; o < 8; o <<= 1)     // butterfly over dpart lanes
                    s += __shfl_xor_sync(0xffffffffu, s, o);

                float p = ex2(s);
                const bool valid = (wku >= sw) && (wku <= sw + 6);
                p = valid ? p : 0.f;
                vsum += p;

                const ull pp = pk2(p, p);
                const float* vp = vbuf + wkey * KST + (dpart << 2);
#pragma unroll
                for (int i = 0; i < 4; ++i) {
                    const ulonglong2 v2 = *(const ulonglong2*)(vp + (i << 5));
                    ffma2(acc[2*i],   pp, v2.x);
                    ffma2(acc[2*i+1], pp, v2.y);
                }
            }
        }
    }

    // ---- finalize: out = acc / vsum ----
    const float inv = 1.0f / vsum;
    float* op = O + ((size_t)((t * Hz + hq) * Wz + wq) * 8 + head) * 128 + (dpart << 2);
#pragma unroll
    for (int i = 0; i < 4; ++i) {
        float x0, y0, x1, y1;
        asm("mov.b64 {%0, %1}, %2;" : "=f"(x0), "=f"(y0) : "l"(acc[2*i]));
        asm("mov.b64 {%0, %1}, %2;" : "=f"(x1), "=f"(y1) : "l"(acc[2*i+1]));
        float4 o4;
        o4.x = x0 * inv; o4.y = y0 * inv; o4.z = x1 * inv; o4.w = y1 * inv;
        *(float4*)(op + (i << 5)) = o4;
    }
}

extern "C" void kernel_launch(void* const* d_in, const int* in_sizes, int n_in,
                              void* d_out, int out_size) {
    const float* q = (const float*)d_in[0];
    const float* k = (const float*)d_in[1];
    const float* v = (const float*)d_in[2];
    (void)in_sizes; (void)n_in; (void)out_size;
    dim3 grid(Tz * (Hz / 2), 8);      // (t, h-pair) x head
    na3d_fwd<<<grid, 512>>>(q, k, v, (float*)d_out);
}

// round 5
// speedup vs baseline: 2.9745x; 2.0592x over previous
#include <cuda_runtime.h>

// NA3D fp32, B=1, T=16, H=32, W=32, nh=8, D=128, window (3,7,7).
// CTA = (t, h-pair, head): 64 queries (2h x 32w), 256 threads = 8 warps.
// Warp = 4 w-queries (octets g=0..3), each lane holds BOTH h-queries (r=2)
// for its (w, 16-dim) fragment -> each K/V byte received feeds 2 queries.
// Each octet iterates its OWN query's exact 7-key w-window (no w-waste).
// Online max-free softmax, f32x2 FMAs, zero data-dependent branches.

#define Tz 16
#define Hz 32
#define Wz 32
#define QSCALE 0.12751743f           // 128^-0.5 * log2(e)

typedef unsigned long long ull;

__device__ __forceinline__ void ffma2(ull& acc, ull a, ull b) {
    asm("fma.rn.f32x2 %0, %1, %2, %0;" : "+l"(acc) : "l"(a), "l"(b));
}
__device__ __forceinline__ ull pk2(float x, float y) {
    ull r; asm("mov.b64 %0, {%1, %2};" : "=l"(r) : "f"(x), "f"(y)); return r;
}
__device__ __forceinline__ float sum2(ull a) {
    float x, y; asm("mov.b64 {%0, %1}, %2;" : "=f"(x), "=f"(y) : "l"(a)); return x + y;
}
__device__ __forceinline__ float ex2(float x) {
    float r; asm("ex2.approx.f32 %0, %1;" : "=f"(r) : "f"(x)); return r;
}

__global__ void __launch_bounds__(256) na3d_fwd(
    const float* __restrict__ Q, const float* __restrict__ K,
    const float* __restrict__ V, float* __restrict__ O)
{
    __shared__ __align__(16) float kbuf[32 * 128];   // one h-row: 32 keys x 128 dims
    __shared__ __align__(16) float vbuf[32 * 128];

    const int bx = blockIdx.x;                 // t*16 + h0/2
    const int head = blockIdx.y;
    const int t = bx >> 4, h0 = (bx & 15) << 1;
    const int tid = threadIdx.x;
    const int warp = tid >> 5, lane = tid & 31;
    const int g = lane >> 3, dpart = lane & 7;

    const int wq = (warp << 2) + g;            // this octet's w-query
    const int st  = min(max(t - 1, 0), Tz - 3);
    const int sh0 = min(max(h0 - 3, 0), Hz - 7);       // h0 window start (CTA-uniform)
    const int sh1 = min(max(h0 - 2, 0), Hz - 7);       // h0+1 window start
    const int sw  = min(max(wq - 3, 0), Wz - 7);       // octet's w window start
    const int hb  = sh0;                                // union h-row base (8 rows)

    // ---- Q fragments for both h-queries: dims {dpart*4 + 32*i + 0..3} ----
    ull qr0[8], qr1[8];
    {
        const size_t q0off = ((size_t)((t * Hz + h0) * Wz + wq) * 8 + head) * 128 + (dpart << 2);
#pragma unroll
        for (int i = 0; i < 4; ++i) {
            float4 a = *(const float4*)(Q + q0off + (i << 5));
            float4 b = *(const float4*)(Q + q0off + (size_t)Wz * 1024 + (i << 5)); // h0+1
            qr0[2*i]   = pk2(a.x * QSCALE, a.y * QSCALE);
            qr0[2*i+1] = pk2(a.z * QSCALE, a.w * QSCALE);
            qr1[2*i]   = pk2(b.x * QSCALE, b.y * QSCALE);
            qr1[2*i+1] = pk2(b.z * QSCALE, b.w * QSCALE);
        }
    }

    ull acc0[8], acc1[8];
#pragma unroll
    for (int i = 0; i < 8; ++i) { acc0[i] = 0ull; acc1[i] = 0ull; }
    float vsum0 = 0.f, vsum1 = 0.f;

#pragma unroll 1
    for (int rr = 0; rr < 24; ++rr) {          // 3 dt x 8 union h-rows
        const int dt = rr >> 3, j = rr & 7;
        const int hh_u = hb + j;               // unclamped union row
        const int hh = min(hh_u, Hz - 1);
        const size_t roff = ((size_t)(((st + dt) * Hz + hh) * Wz) * 8 + head) * 128;
        const float4* ksrc = (const float4*)(K + roff);
        const float4* vsrc = (const float4*)(V + roff);

        __syncthreads();
#pragma unroll
        for (int g0 = 0; g0 < 8; ++g0) {       // stage K row + V row (32KB)
            const int idx = tid + (g0 << 8);   // 0..2047 float4 granules
            const int wp = (idx >> 5) & 31, d4 = idx & 31;
            if (idx < 1024) ((float4*)kbuf)[idx] = ksrc[wp * 256 + d4];
            else            ((float4*)vbuf)[idx - 1024] = vsrc[wp * 256 + d4];
        }
        __syncthreads();

        const bool v0 = (hh_u >= sh0) & (hh_u <= sh0 + 6);   // CTA-uniform
        const bool v1 = (hh_u >= sh1) & (hh_u <= sh1 + 6);
        if (!(v0 | v1)) continue;              // uniform skip (rare edge rows)

#pragma unroll
        for (int kk = 0; kk < 7; ++kk) {       // exact per-octet key window
            const float* kp = kbuf + ((sw + kk) << 7) + (dpart << 2);
            ull a0A = 0ull, a0B = 0ull, a1A = 0ull, a1B = 0ull;
#pragma unroll
            for (int i = 0; i < 4; ++i) {
                const ulonglong2 k2 = *(const ulonglong2*)(kp + (i << 5));
                ffma2(a0A, qr0[2*i],   k2.x);
                ffma2(a0B, qr0[2*i+1], k2.y);
                ffma2(a1A, qr1[2*i],   k2.x);
                ffma2(a1B, qr1[2*i+1], k2.y);
            }
            float s0 = sum2(a0A) + sum2(a0B);
            float s1 = sum2(a1A) + sum2(a1B);
#pragma unroll
            for (int o = 1; o < 8; o <<= 1) {  // butterfly within octet
                s0 += __shfl_xor_sync(0xffffffffu, s0, o);
                s1 += __shfl_xor_sync(0xffffffffu, s1, o);
            }
            float p0 = v0 ? ex2(s0) : 0.f;
            float p1 = v1 ? ex2(s1) : 0.f;
            vsum0 += p0; vsum1 += p1;
            const ull pp0 = pk2(p0, p0);
            const ull pp1 = pk2(p1, p1);

            const float* vp = vbuf + ((sw + kk) << 7) + (dpart << 2);
#pragma unroll
            for (int i = 0; i < 4; ++i) {
                const ulonglong2 v2 = *(const ulonglong2*)(vp + (i << 5));
                ffma2(acc0[2*i],   pp0, v2.x);
                ffma2(acc0[2*i+1], pp0, v2.y);
                ffma2(acc1[2*i],   pp1, v2.x);
                ffma2(acc1[2*i+1], pp1, v2.y);
            }
        }
    }

    // ---- finalize both queries ----
    const float inv0 = 1.0f / vsum0;
    const float inv1 = 1.0f / vsum1;
    const size_t o0 = ((size_t)((t * Hz + h0) * Wz + wq) * 8 + head) * 128 + (dpart << 2);
#pragma unroll
    for (int i = 0; i < 4; ++i) {
        float x0, y0, x1, y1;
        asm("mov.b64 {%0, %1}, %2;" : "=f"(x0), "=f"(y0) : "l"(acc0[2*i]));
        asm("mov.b64 {%0, %1}, %2;" : "=f"(x1), "=f"(y1) : "l"(acc0[2*i+1]));
        float4 u; u.x = x0 * inv0; u.y = y0 * inv0; u.z = x1 * inv0; u.w = y1 * inv0;
        *(float4*)(O + o0 + (i << 5)) = u;

        asm("mov.b64 {%0, %1}, %2;" : "=f"(x0), "=f"(y0) : "l"(acc1[2*i]));
        asm("mov.b64 {%0, %1}, %2;" : "=f"(x1), "=f"(y1) : "l"(acc1[2*i+1]));
        float4 w; w.x = x0 * inv1; w.y = y0 * inv1; w.z = x1 * inv1; w.w = y1 * inv1;
        *(float4*)(O + o0 + (size_t)Wz * 1024 + (i << 5)) = w;
    }
}

extern "C" void kernel_launch(void* const* d_in, const int* in_sizes, int n_in,
                              void* d_out, int out_size) {
    const float* q = (const float*)d_in[0];
    const float* k = (const float*)d_in[1];
    const float* v = (const float*)d_in[2];
    (void)in_sizes; (void)n_in; (void)out_size;
    dim3 grid(Tz * (Hz / 2), 8);      // (t, h-pair) x head
    na3d_fwd<<<grid, 256>>>(q, k, v, (float*)d_out);
}

// round 6
// speedup vs baseline: 4.2393x; 1.4252x over previous
#include <cuda_runtime.h>
#include <cuda_fp16.h>
#include <cstdint>

// NA3D fp32 in/out, B=1, T=16, H=32, W=32, nh=8, D=128, window (3,7,7).
// Register-MMA (m16n8k16 fp16 -> f32) dense-halo formulation.
// CTA = (t, h-pair, head), 128 thr = 4 warps; warp = tile of 16 queries
// (2h x 8w) vs 16-key slabs (w-span 14 + 2 masked) per staged (dt,dh) row.
// K/V/Q staged fp16 (272B pitch, conflict-free ldmatrix). Max-free ex2
// softmax; P = C-frag == A-frag layout (no smem roundtrip).

#define Tz 16
#define Hz 32
#define Wz 32
#define QSCALE 0.12751744f          // 128^-0.5 * log2(e)
#define PITCH 136                   // halves per staged vector row (272 B)

__device__ __forceinline__ uint32_t smaddr(const void* p) {
    uint32_t a;
    asm("{ .reg .u64 t; cvta.to.shared.u64 t, %1; cvt.u32.u64 %0, t; }"
        : "=r"(a) : "l"(p));
    return a;
}
__device__ __forceinline__ void ldsm4(uint32_t& r0, uint32_t& r1, uint32_t& r2,
                                      uint32_t& r3, uint32_t a) {
    asm volatile("ldmatrix.sync.aligned.m8n8.x4.shared.b16 {%0,%1,%2,%3}, [%4];"
                 : "=r"(r0), "=r"(r1), "=r"(r2), "=r"(r3) : "r"(a));
}
__device__ __forceinline__ void ldsm4t(uint32_t& r0, uint32_t& r1, uint32_t& r2,
                                       uint32_t& r3, uint32_t a) {
    asm volatile("ldmatrix.sync.aligned.m8n8.x4.trans.shared.b16 {%0,%1,%2,%3}, [%4];"
                 : "=r"(r0), "=r"(r1), "=r"(r2), "=r"(r3) : "r"(a));
}
__device__ __forceinline__ void mma16816(float* d, const uint32_t* a,
                                         uint32_t b0, uint32_t b1) {
    asm volatile("mma.sync.aligned.m16n8k16.row.col.f32.f16.f16.f32 "
                 "{%0,%1,%2,%3}, {%4,%5,%6,%7}, {%8,%9}, {%0,%1,%2,%3};"
                 : "+f"(d[0]), "+f"(d[1]), "+f"(d[2]), "+f"(d[3])
                 : "r"(a[0]), "r"(a[1]), "r"(a[2]), "r"(a[3]), "r"(b0), "r"(b1));
}
__device__ __forceinline__ float ex2f(float x) {
    float r; asm("ex2.approx.f32 %0, %1;" : "=f"(r) : "f"(x)); return r;
}
__device__ __forceinline__ uint32_t f2h2(float a, float b) {
    __half2 h = __floats2half2_rn(a, b);
    return *reinterpret_cast<uint32_t*>(&h);
}

__global__ void __launch_bounds__(128, 3) na3d_mma(
    const float* __restrict__ Q, const float* __restrict__ K,
    const float* __restrict__ V, float* __restrict__ O)
{
    __shared__ __align__(16) __half qs[64 * PITCH];
    __shared__ __align__(16) __half ksm[32 * PITCH];
    __shared__ __align__(16) __half vsm[32 * PITCH];

    const int bx = blockIdx.x;              // t*16 + h0/2
    const int head = blockIdx.y;
    const int t = bx >> 4, h0 = (bx & 15) << 1;
    const int tid = threadIdx.x, warp = tid >> 5, lane = tid & 31;

    const int st  = min(max(t - 1, 0), Tz - 3);
    const int sh0 = min(max(h0 - 3, 0), Hz - 7);
    const int sh1 = min(max(h0 - 2, 0), Hz - 7);
    const int dj  = sh1 - sh0;              // 0 or 1

    // ---------- stage Q as scaled fp16 (log2 domain) ----------
    for (int c = tid; c < 512; c += 128) {  // chunk = (query, 16-dim seg)
        const int qi = c >> 3, seg = c & 7;
        const int wtile = qi >> 4, m = qi & 15;
        const int h_i = m >> 3, w = (wtile << 3) + (m & 7);
        const float4* src = (const float4*)(Q +
            ((((size_t)t * Hz + h0 + h_i) * Wz + w) * 8 + head) * 128 + seg * 16);
        float4 f0 = src[0], f1 = src[1], f2 = src[2], f3 = src[3];
        uint4 u0, u1;
        u0.x = f2h2(f0.x * QSCALE, f0.y * QSCALE);
        u0.y = f2h2(f0.z * QSCALE, f0.w * QSCALE);
        u0.z = f2h2(f1.x * QSCALE, f1.y * QSCALE);
        u0.w = f2h2(f1.z * QSCALE, f1.w * QSCALE);
        u1.x = f2h2(f2.x * QSCALE, f2.y * QSCALE);
        u1.y = f2h2(f2.z * QSCALE, f2.w * QSCALE);
        u1.z = f2h2(f3.x * QSCALE, f3.y * QSCALE);
        u1.w = f2h2(f3.z * QSCALE, f3.w * QSCALE);
        uint4* dst = (uint4*)(qs + qi * PITCH + seg * 16);
        dst[0] = u0; dst[1] = u1;
    }
    __syncthreads();

    // ---------- per-warp constants ----------
    const int w0t   = warp << 3;                       // tile query-w base
    const int wbase = min(max(w0t - 3, 0), Wz - 14);   // key w-span base (14 wide)
    const int g = lane >> 2, tig = lane & 3;
    const int sw = min(max(w0t + g - 3, 0), Wz - 7);   // this lane-row's window start

    const uint32_t qs0 = smaddr(qs), ks0 = smaddr(ksm), vs0 = smaddr(vsm);

    // Q A-frags (resident): 8 ksteps x 4 regs
    uint32_t afrag[8][4];
    {
        const uint32_t a0 = qs0 +
            (((warp << 4) + (lane & 15)) * PITCH + ((lane >> 4) << 3)) * 2;
#pragma unroll
        for (int ksx = 0; ksx < 8; ++ksx)
            ldsm4(afrag[ksx][0], afrag[ksx][1], afrag[ksx][2], afrag[ksx][3],
                  a0 + ksx * 32);
    }
    // K B-frag ldmatrix lane address (content varies per row, address fixed)
    const int kkey = min(wbase + ((lane >> 4) << 3) + (lane & 7), 31);
    const uint32_t kaddr0 = ks0 + (kkey * PITCH + (lane & 8)) * 2;
    // V B-frag (trans) lane address
    const int vkey = min(wbase + (lane & 15), 31);
    const uint32_t vaddr0 = vs0 + (vkey * PITCH + ((lane & 16) >> 1)) * 2;

    float o[16][4];
#pragma unroll
    for (int i = 0; i < 16; ++i) { o[i][0] = o[i][1] = o[i][2] = o[i][3] = 0.f; }
    float vlo = 0.f, vhi = 0.f;

    // ================= row loop: 3 dt x 8 union dh =================
    for (int rr = 0; rr < 24; ++rr) {
        const int dt = rr >> 3, j = rr & 7;
        const bool vh0 = (j <= 6);
        const bool vh1 = (j >= dj) && (j <= dj + 6);
        const bool rowv = vh0 | vh1;                   // CTA-uniform
        const int hh = min(sh0 + j, Hz - 1);
        const size_t roff = (((size_t)(st + dt) * Hz + hh) * Wz * 8 + head) * 128;

        __syncthreads();
        if (rowv) {
            for (int c = tid; c < 512; c += 128) {     // 256 K + 256 V chunks
                const int key = (c >> 3) & 31, seg = c & 7;
                const float4* src = (const float4*)(((c < 256) ? K : V) +
                    roff + key * 1024 + seg * 16);
                float4 f0 = src[0], f1 = src[1], f2 = src[2], f3 = src[3];
                uint4 u0, u1;
                u0.x = f2h2(f0.x, f0.y); u0.y = f2h2(f0.z, f0.w);
                u0.z = f2h2(f1.x, f1.y); u0.w = f2h2(f1.z, f1.w);
                u1.x = f2h2(f2.x, f2.y); u1.y = f2h2(f2.z, f2.w);
                u1.z = f2h2(f3.x, f3.y); u1.w = f2h2(f3.z, f3.w);
                uint4* dst = (uint4*)(((c < 256) ? ksm : vsm) + key * PITCH + seg * 16);
                dst[0] = u0; dst[1] = u1;
            }
        }
        __syncthreads();
        if (!rowv) continue;

        // ---- QK: S[16q x 16keys] ----
        float s0[4] = {0.f, 0.f, 0.f, 0.f}, s1[4] = {0.f, 0.f, 0.f, 0.f};
#pragma unroll
        for (int ksx = 0; ksx < 8; ++ksx) {
            uint32_t r0, r1, r2, r3;
            ldsm4(r0, r1, r2, r3, kaddr0 + ksx * 32);
            mma16816(s0, afrag[ksx], r0, r1);
            mma16816(s1, afrag[ksx], r2, r3);
        }

        // ---- mask + ex2 + pack to P A-frag ----
        const int wk0 = wbase + 2 * tig;               // nt0 key w base
        const int wk1 = wk0 + 8;                       // nt1
        float p00 = ((unsigned)(wk0     - sw) <= 6u && vh0) ? ex2f(s0[0]) : 0.f;
        float p01 = ((unsigned)(wk0 + 1 - sw) <= 6u && vh0) ? ex2f(s0[1]) : 0.f;
        float p02 = ((unsigned)(wk0     - sw) <= 6u && vh1) ? ex2f(s0[2]) : 0.f;
        float p03 = ((unsigned)(wk0 + 1 - sw) <= 6u && vh1) ? ex2f(s0[3]) : 0.f;
        float p10 = ((unsigned)(wk1     - sw) <= 6u && vh0) ? ex2f(s1[0]) : 0.f;
        float p11 = ((unsigned)(wk1 + 1 - sw) <= 6u && vh0) ? ex2f(s1[1]) : 0.f;
        float p12 = ((unsigned)(wk1     - sw) <= 6u && vh1) ? ex2f(s1[2]) : 0.f;
        float p13 = ((unsigned)(wk1 + 1 - sw) <= 6u && vh1) ? ex2f(s1[3]) : 0.f;
        vlo += (p00 + p01) + (p10 + p11);
        vhi += (p02 + p03) + (p12 + p13);
        uint32_t pa[4];
        pa[0] = f2h2(p00, p01); pa[1] = f2h2(p02, p03);
        pa[2] = f2h2(p10, p11); pa[3] = f2h2(p12, p13);

        // ---- PV: O[16q x 128d] += P x V ----
#pragma unroll
        for (int d8 = 0; d8 < 8; ++d8) {
            uint32_t r0, r1, r2, r3;
            ldsm4t(r0, r1, r2, r3, vaddr0 + d8 * 32);
            mma16816(o[2 * d8],     pa, r0, r1);
            mma16816(o[2 * d8 + 1], pa, r2, r3);
        }
    }

    // ---- vsum reduce over quad (same query rows) ----
    vlo += __shfl_xor_sync(0xffffffffu, vlo, 1);
    vlo += __shfl_xor_sync(0xffffffffu, vlo, 2);
    vhi += __shfl_xor_sync(0xffffffffu, vhi, 1);
    vhi += __shfl_xor_sync(0xffffffffu, vhi, 2);
    const float ilo = 1.0f / vlo, ihi = 1.0f / vhi;

    // ---- write out ----
    const int wq = w0t + g;
    float* olo = O + ((((size_t)t * Hz + h0    ) * Wz + wq) * 8 + head) * 128 + 2 * tig;
    float* ohi = O + ((((size_t)t * Hz + h0 + 1) * Wz + wq) * 8 + head) * 128 + 2 * tig;
#pragma unroll
    for (int nt = 0; nt < 16; ++nt) {
        float2 lo; lo.x = o[nt][0] * ilo; lo.y = o[nt][1] * ilo;
        float2 hi; hi.x = o[nt][2] * ihi; hi.y = o[nt][3] * ihi;
        *(float2*)(olo + nt * 8) = lo;
        *(float2*)(ohi + nt * 8) = hi;
    }
}

extern "C" void kernel_launch(void* const* d_in, const int* in_sizes, int n_in,
                              void* d_out, int out_size) {
    const float* q = (const float*)d_in[0];
    const float* k = (const float*)d_in[1];
    const float* v = (const float*)d_in[2];
    (void)in_sizes; (void)n_in; (void)out_size;
    dim3 grid(Tz * (Hz / 2), 8);
    na3d_mma<<<grid, 128>>>(q, k, v, (float*)d_out);
}

// round 8
// speedup vs baseline: 7.5441x; 1.7796x over previous
#include <cuda_runtime.h>
#include <cuda_fp16.h>
#include <cstdint>

// NA3D fp32 in/out. B=1, T=16, H=32, W=32, nh=8, D=128, window (3,7,7).
// Prepass: K,V -> fp16 __device__ scratch (once). Main: register-MMA
// m16n8k16, CTA = (t, h-quad, head) = 128 queries, 256 thr = 8 warps
// (2 h-pairs x 4 w-tiles). K/V rows (10 union-h per dt, 30 total) staged
// fp16 via cp.async double-buffer. Warp-level QK/mask/ex2/PV identical to
// the validated round-6 core.

#define Tz 16
#define Hz 32
#define Wz 32
#define NHEAD 8
#define DD 128
#define QSCALE 0.12751744f          // 128^-0.5 * log2(e)
#define PITCH 136                   // halves per key row in smem (272 B)
#define BUFB (32 * PITCH * 2)       // bytes per K or V stage buffer (8704)
#define ELEMS (Tz * Hz * Wz * NHEAD * DD)

__device__ __half Kh[ELEMS];
__device__ __half Vh[ELEMS];

__device__ __forceinline__ uint32_t smaddr(const void* p) {
    uint32_t a;
    asm("{ .reg .u64 t; cvta.to.shared.u64 t, %1; cvt.u32.u64 %0, t; }"
        : "=r"(a) : "l"(p));
    return a;
}
__device__ __forceinline__ void ldsm4(uint32_t& r0, uint32_t& r1, uint32_t& r2,
                                      uint32_t& r3, uint32_t a) {
    asm volatile("ldmatrix.sync.aligned.m8n8.x4.shared.b16 {%0,%1,%2,%3}, [%4];"
                 : "=r"(r0), "=r"(r1), "=r"(r2), "=r"(r3) : "r"(a));
}
__device__ __forceinline__ void ldsm4t(uint32_t& r0, uint32_t& r1, uint32_t& r2,
                                       uint32_t& r3, uint32_t a) {
    asm volatile("ldmatrix.sync.aligned.m8n8.x4.trans.shared.b16 {%0,%1,%2,%3}, [%4];"
                 : "=r"(r0), "=r"(r1), "=r"(r2), "=r"(r3) : "r"(a));
}
__device__ __forceinline__ void mma16816(float* d, const uint32_t* a,
                                         uint32_t b0, uint32_t b1) {
    asm volatile("mma.sync.aligned.m16n8k16.row.col.f32.f16.f16.f32 "
                 "{%0,%1,%2,%3}, {%4,%5,%6,%7}, {%8,%9}, {%0,%1,%2,%3};"
                 : "+f"(d[0]), "+f"(d[1]), "+f"(d[2]), "+f"(d[3])
                 : "r"(a[0]), "r"(a[1]), "r"(a[2]), "r"(a[3]), "r"(b0), "r"(b1));
}
__device__ __forceinline__ float ex2f(float x) {
    float r; asm("ex2.approx.f32 %0, %1;" : "=f"(r) : "f"(x)); return r;
}
__device__ __forceinline__ uint32_t f2h2(float a, float b) {
    __half2 h = __floats2half2_rn(a, b);
    return *reinterpret_cast<uint32_t*>(&h);
}
__device__ __forceinline__ void cpa16(uint32_t dst, const void* src) {
    asm volatile("cp.async.ca.shared.global [%0], [%1], 16;"
                 :: "r"(dst), "l"(src));
}

// ---------------- prepass: fp32 -> fp16 for K and V ----------------
__global__ void __launch_bounds__(256) cvt_kv(const float* __restrict__ K,
                                              const float* __restrict__ V) {
    const size_t i = (size_t)blockIdx.x * 256 + threadIdx.x;   // 8-half granule
    const float4* src = (const float4*)(blockIdx.y ? V : K) + 2 * i;
    uint4* dst = (uint4*)(blockIdx.y ? Vh : Kh) + i;
    const float4 a = src[0], b = src[1];
    uint4 u;
    u.x = f2h2(a.x, a.y); u.y = f2h2(a.z, a.w);
    u.z = f2h2(b.x, b.y); u.w = f2h2(b.z, b.w);
    *dst = u;
}

// ---------------- main kernel ----------------
__global__ void __launch_bounds__(256, 1) na3d_mma(
    const float* __restrict__ Q, float* __restrict__ O)
{
    __shared__ __align__(16) __half ksm[2][32 * PITCH];
    __shared__ __align__(16) __half vsm[2][32 * PITCH];

    const int bx = blockIdx.x;               // t*8 + hq4
    const int head = blockIdx.y;
    const int t = bx >> 3, h0q = (bx & 7) << 2;
    const int tid = threadIdx.x, warp = tid >> 5, lane = tid & 31;
    const int hp = warp >> 2, wtile = warp & 3;
    const int h0 = h0q + (hp << 1);          // this warp's lower query h

    const int st  = min(max(t - 1, 0), Tz - 3);
    const int hb  = min(max(h0q - 3, 0), Hz - 7);   // union h-row base (10 rows/dt)
    const int sh0 = min(max(h0 - 3, 0), Hz - 7);
    const int sh1 = min(max(h0 - 2, 0), Hz - 7);

    const int w0t   = wtile << 3;
    const int wbase = min(max(w0t - 3, 0), Wz - 14);
    const int g = lane >> 2, tig = lane & 3;
    const int sw = min(max(w0t + g - 3, 0), Wz - 7);

    // ---- Q A-frags direct from fp32 global (scaled, once) ----
    uint32_t afrag[8][4];
    {
        const float* q0 = Q + (((size_t)(t * Hz + h0) * Wz + (w0t + g)) * NHEAD + head) * DD;
        const float* q1 = q0 + (size_t)Wz * NHEAD * DD;     // h0+1
#pragma unroll
        for (int ks = 0; ks < 8; ++ks) {
            const int d0 = ks * 16 + 2 * tig;
            float2 a = *(const float2*)(q0 + d0);
            float2 b = *(const float2*)(q1 + d0);
            float2 c = *(const float2*)(q0 + d0 + 8);
            float2 d = *(const float2*)(q1 + d0 + 8);
            afrag[ks][0] = f2h2(a.x * QSCALE, a.y * QSCALE);
            afrag[ks][1] = f2h2(b.x * QSCALE, b.y * QSCALE);
            afrag[ks][2] = f2h2(c.x * QSCALE, c.y * QSCALE);
            afrag[ks][3] = f2h2(d.x * QSCALE, d.y * QSCALE);
        }
    }

    const uint32_t ks0 = smaddr(ksm), vs0 = smaddr(vsm);
    const int kkey = min(wbase + ((lane >> 4) << 3) + (lane & 7), 31);
    const uint32_t kaddrb = (kkey * PITCH + (lane & 8)) * 2;
    const int vkey = min(wbase + (lane & 15), 31);
    const uint32_t vaddrb = (vkey * PITCH + ((lane & 16) >> 1)) * 2;

    // staging chunk constants: this thread's 2 K + 2 V cp.asyncs per row
    const int c0 = tid, c1 = tid + 256;           // chunks 0..511
    const int key0 = c0 >> 4, seg0 = c0 & 15;
    const int key1 = c1 >> 4, seg1 = c1 & 15;

    auto issue_row = [&](int rr) {
        const int dt = rr / 10, j = rr - dt * 10;
        const int hh = min(hb + j, Hz - 1);
        const size_t base = (((size_t)(st + dt) * Hz + hh) * Wz * NHEAD + head) * (size_t)DD;
        const uint32_t bo = (rr & 1) ? BUFB : 0;
        cpa16(ks0 + bo + key0 * 272 + seg0 * 16, Kh + base + key0 * 1024 + seg0 * 8);
        cpa16(ks0 + bo + key1 * 272 + seg1 * 16, Kh + base + key1 * 1024 + seg1 * 8);
        cpa16(vs0 + bo + key0 * 272 + seg0 * 16, Vh + base + key0 * 1024 + seg0 * 8);
        cpa16(vs0 + bo + key1 * 272 + seg1 * 16, Vh + base + key1 * 1024 + seg1 * 8);
    };

    float o[16][4];
#pragma unroll
    for (int i = 0; i < 16; ++i) { o[i][0] = o[i][1] = o[i][2] = o[i][3] = 0.f; }
    float vlo = 0.f, vhi = 0.f;

    issue_row(0);
    asm volatile("cp.async.commit_group;");

    for (int rr = 0; rr < 30; ++rr) {
        if (rr < 29) {
            issue_row(rr + 1);
            asm volatile("cp.async.commit_group;");
            asm volatile("cp.async.wait_group 1;");
        } else {
            asm volatile("cp.async.wait_group 0;");
        }
        __syncthreads();

        const int dt = rr / 10, j = rr - dt * 10;
        const int hh_u = hb + j;
        const bool vh0 = (hh_u >= sh0) & (hh_u <= sh0 + 6);
        const bool vh1 = (hh_u >= sh1) & (hh_u <= sh1 + 6);
        if (vh0 | vh1) {
            const uint32_t bo = (rr & 1) ? BUFB : 0;
            const uint32_t kaddr = ks0 + bo + kaddrb;
            const uint32_t vaddr = vs0 + bo + vaddrb;

            // ---- QK: S[16q x 16keys] ----
            float s0[4] = {0.f, 0.f, 0.f, 0.f}, s1[4] = {0.f, 0.f, 0.f, 0.f};
#pragma unroll
            for (int ks = 0; ks < 8; ++ks) {
                uint32_t r0, r1, r2, r3;
                ldsm4(r0, r1, r2, r3, kaddr + ks * 32);
                mma16816(s0, afrag[ks], r0, r1);
                mma16816(s1, afrag[ks], r2, r3);
            }

            // ---- mask + ex2 + pack P ----
            const int wk0 = wbase + 2 * tig;
            const int wk1 = wk0 + 8;
            float p00 = ((unsigned)(wk0     - sw) <= 6u && vh0) ? ex2f(s0[0]) : 0.f;
            float p01 = ((unsigned)(wk0 + 1 - sw) <= 6u && vh0) ? ex2f(s0[1]) : 0.f;
            float p02 = ((unsigned)(wk0     - sw) <= 6u && vh1) ? ex2f(s0[2]) : 0.f;
            float p03 = ((unsigned)(wk0 + 1 - sw) <= 6u && vh1) ? ex2f(s0[3]) : 0.f;
            float p10 = ((unsigned)(wk1     - sw) <= 6u && vh0) ? ex2f(s1[0]) : 0.f;
            float p11 = ((unsigned)(wk1 + 1 - sw) <= 6u && vh0) ? ex2f(s1[1]) : 0.f;
            float p12 = ((unsigned)(wk1     - sw) <= 6u && vh1) ? ex2f(s1[2]) : 0.f;
            float p13 = ((unsigned)(wk1 + 1 - sw) <= 6u && vh1) ? ex2f(s1[3]) : 0.f;
            vlo += (p00 + p01) + (p10 + p11);
            vhi += (p02 + p03) + (p12 + p13);
            uint32_t pa[4];
            pa[0] = f2h2(p00, p01); pa[1] = f2h2(p02, p03);
            pa[2] = f2h2(p10, p11); pa[3] = f2h2(p12, p13);

            // ---- PV ----
#pragma unroll
            for (int d8 = 0; d8 < 8; ++d8) {
                uint32_t r0, r1, r2, r3;
                ldsm4t(r0, r1, r2, r3, vaddr + d8 * 32);
                mma16816(o[2 * d8],     pa, r0, r1);
                mma16816(o[2 * d8 + 1], pa, r2, r3);
            }
        }
        __syncthreads();
    }

    // ---- vsum reduce over quad, finalize ----
    vlo += __shfl_xor_sync(0xffffffffu, vlo, 1);
    vlo += __shfl_xor_sync(0xffffffffu, vlo, 2);
    vhi += __shfl_xor_sync(0xffffffffu, vhi, 1);
    vhi += __shfl_xor_sync(0xffffffffu, vhi, 2);
    const float ilo = 1.0f / vlo, ihi = 1.0f / vhi;

    const int wq = w0t + g;
    float* olo = O + ((((size_t)t * Hz + h0    ) * Wz + wq) * NHEAD + head) * DD + 2 * tig;
    float* ohi = O + ((((size_t)t * Hz + h0 + 1) * Wz + wq) * NHEAD + head) * DD + 2 * tig;
#pragma unroll
    for (int nt = 0; nt < 16; ++nt) {
        float2 lo; lo.x = o[nt][0] * ilo; lo.y = o[nt][1] * ilo;
        float2 hi; hi.x = o[nt][2] * ihi; hi.y = o[nt][3] * ihi;
        *(float2*)(olo + nt * 8) = lo;
        *(float2*)(ohi + nt * 8) = hi;
    }
}

extern "C" void kernel_launch(void* const* d_in, const int* in_sizes, int n_in,
                              void* d_out, int out_size) {
    const float* q = (const float*)d_in[0];
    const float* k = (const float*)d_in[1];
    const float* v = (const float*)d_in[2];
    (void)in_sizes; (void)n_in; (void)out_size;

    dim3 cg(ELEMS / 8 / 256, 2);             // K and V
    cvt_kv<<<cg, 256>>>(k, v);

    dim3 grid(Tz * (Hz / 4), NHEAD);         // (t, h-quad) x head
    na3d_mma<<<grid, 256>>>(q, (float*)d_out);
}